// round 12
// baseline (speedup 1.0000x reference)
#include <cuda_runtime.h>
#include <cuda_bf16.h>
#include <math.h>
#include <stdint.h>

#define N_NODES 50000
#define E_EDGES 800000
#define CH 128
#define NEG_SLOPE 0.2f
#define N_TILES ((N_NODES + 127) / 128)   // 391
#define GEMM_GRID 148

// ---------------- scratch (static device globals) ----------------
__device__ float g_xl[N_NODES * CH];
__device__ float g_xr[N_NODES * CH];
__device__ float g_h[N_NODES * CH];
__device__ int   g_deg[N_NODES];
__device__ int   g_cur[N_NODES];
__device__ int   g_off[N_NODES + 1];
__device__ int   g_srcs[E_EDGES];
// weight images: [layer][Lhi, Llo, Rhi, Rlo], each [n=128][k stride 136] bf16
#define KS 136
#define IMG_ELEMS (128 * KS)            // 17408
__device__ __align__(16) __nv_bfloat16 g_Bimg[2 * 4 * IMG_ELEMS];

__device__ __forceinline__ uint32_t smem_u32(const void* p) {
    uint32_t a;
    asm("{ .reg .u64 t; cvta.to.shared.u64 t, %1; cvt.u32.u64 %0, t; }"
        : "=r"(a) : "l"(p));
    return a;
}

#define LDSM_X4(r0, r1, r2, r3, addr)                                         \
    asm volatile("ldmatrix.sync.aligned.m8n8.x4.shared.b16 {%0,%1,%2,%3}, [%4];" \
                 : "=r"(r0), "=r"(r1), "=r"(r2), "=r"(r3) : "r"(addr))

__device__ __forceinline__ void mma_bf16(float* c, const uint32_t* a,
                                         uint32_t b0, uint32_t b1) {
    asm volatile(
        "mma.sync.aligned.m16n8k16.row.col.f32.bf16.bf16.f32 "
        "{%0,%1,%2,%3}, {%4,%5,%6,%7}, {%8,%9}, {%0,%1,%2,%3};"
        : "+f"(c[0]), "+f"(c[1]), "+f"(c[2]), "+f"(c[3])
        : "r"(a[0]), "r"(a[1]), "r"(a[2]), "r"(a[3]), "r"(b0), "r"(b1));
}

// ============================ weight image prep ============================
__global__ __launch_bounds__(256) void prep_w(
    const float* __restrict__ W1l, const float* __restrict__ W1r,
    const float* __restrict__ W2l, const float* __restrict__ W2r,
    __nv_bfloat16* __restrict__ img)
{
    const int tid = blockIdx.x * 256 + threadIdx.x;   // 65536 total
    const int layer = tid >> 15;
    const int m     = (tid >> 14) & 1;
    const int e     = tid & 16383;
    const int k = e >> 7, n = e & 127;

    const float* W = layer ? (m ? W2r : W2l) : (m ? W1r : W1l);
    const float v = W[k * 128 + n];
    const __nv_bfloat16 hi = __float2bfloat16_rn(v);
    const __nv_bfloat16 lo = __float2bfloat16_rn(v - __bfloat162float(hi));

    const int base = (layer * 4 + m * 2) * IMG_ELEMS;
    img[base + n * KS + k]             = hi;
    img[base + IMG_ELEMS + n * KS + k] = lo;
}

// =============================== CSR build =================================
// 4 edges / thread via int4
__global__ __launch_bounds__(256) void count_deg(const int4* __restrict__ dst4,
                                                 int* __restrict__ deg)
{
    const int i = blockIdx.x * 256 + threadIdx.x;
    if (i < E_EDGES / 4) {
        const int4 d = dst4[i];
        atomicAdd(&deg[d.x], 1);
        atomicAdd(&deg[d.y], 1);
        atomicAdd(&deg[d.z], 1);
        atomicAdd(&deg[d.w], 1);
    }
}

// single block, one barrier phase: per-thread chunk sums -> block scan ->
// second pass writes running prefix.  CHUNK*1024 >= N_NODES.
#define SCAN_CHUNK 49
__global__ __launch_bounds__(1024) void scan_deg(const int* __restrict__ deg,
                                                 int* __restrict__ off,
                                                 int* __restrict__ cur)
{
    __shared__ int wsum[32];
    const int tid = threadIdx.x, lane = tid & 31, wid = tid >> 5;
    const int start = tid * SCAN_CHUNK;

    // pass 1: per-thread sum
    int sum = 0;
    #pragma unroll 7
    for (int j = 0; j < SCAN_CHUNK; j++) {
        const int idx = start + j;
        sum += (idx < N_NODES) ? deg[idx] : 0;
    }

    // block-wide exclusive scan of thread sums
    int s = sum;
    #pragma unroll
    for (int o = 1; o < 32; o <<= 1) {
        int t = __shfl_up_sync(0xffffffffu, s, o);
        if (lane >= o) s += t;
    }
    if (lane == 31) wsum[wid] = s;
    __syncthreads();
    if (wid == 0) {
        int ws = wsum[lane];
        #pragma unroll
        for (int o = 1; o < 32; o <<= 1) {
            int t = __shfl_up_sync(0xffffffffu, ws, o);
            if (lane >= o) ws += t;
        }
        wsum[lane] = ws;
    }
    __syncthreads();
    int run = s - sum + (wid > 0 ? wsum[wid - 1] : 0);   // exclusive base

    // pass 2: write prefix (deg re-read is L2-hot)
    #pragma unroll 7
    for (int j = 0; j < SCAN_CHUNK; j++) {
        const int idx = start + j;
        if (idx < N_NODES) {
            off[idx] = run;
            cur[idx] = run;
            run += deg[idx];
        }
    }
    if (tid == 1023) off[N_NODES] = run;
}

__global__ __launch_bounds__(256) void scatter_csr(
    const int4* __restrict__ src4, const int4* __restrict__ dst4,
    int* __restrict__ cur, int* __restrict__ srcs)
{
    const int i = blockIdx.x * 256 + threadIdx.x;
    if (i >= E_EDGES / 4) return;
    const int4 s = src4[i];
    const int4 d = dst4[i];
    srcs[atomicAdd(&cur[d.x], 1)] = s.x;
    srcs[atomicAdd(&cur[d.y], 1)] = s.y;
    srcs[atomicAdd(&cur[d.z], 1)] = s.z;
    srcs[atomicAdd(&cur[d.w], 1)] = s.w;
}

// ====== persistent mma.sync bf16 split-3 dual GEMM (256 thr, copy-once) ====
#define SA_HI 0
#define SA_LO IMG_ELEMS
#define SB0   (2 * IMG_ELEMS)
#define SM_BYTES (6 * IMG_ELEMS * 2)    // 208896

__global__ __launch_bounds__(256, 1)
void gemm_mma(const float* __restrict__ in, const __nv_bfloat16* __restrict__ img,
              float* __restrict__ outL, float* __restrict__ outR)
{
    extern __shared__ char smem[];
    const uint32_t sb = smem_u32(smem);
    const int tid = threadIdx.x;
    const int lane = tid & 31;
    const int wid = tid >> 5;

    // ---- B: copy 4 pre-split images ONCE ----
    {
        const uint4* gi = (const uint4*)img;
        uint4* si = (uint4*)(smem + SB0 * 2);
        #pragma unroll
        for (int i = 0; i < 34; i++) {
            const int idx = i * 256 + tid;        // 8704 uint4
            si[idx] = gi[idx];
        }
    }

    const int wm = wid & 3, wn = wid >> 2;
    const int row0 = wm * 32, col0 = wn * 64;
    const int lane_r  = lane & 15;
    const int lane_c8 = (lane >> 4) * 8;
    const int sub = lane & 7, sel = lane >> 3;
    const int b_n  = sub + ((sel & 2) ? 8 : 0);
    const int b_k8 = (sel & 1) ? 8 : 0;

    for (int t = blockIdx.x; t < N_TILES; t += GEMM_GRID) {
        const int base = t * 128;

        __syncthreads();

        // ---- A: load fp32 rows, split bf16 hi/lo, store padded ----
        #pragma unroll
        for (int i = 0; i < 16; i++) {
            const int chunk = i * 256 + tid;
            const int row = chunk >> 5;
            const int c4  = chunk & 31;
            int grow = base + row;
            if (grow >= N_NODES) grow = N_NODES - 1;
            const float4 v = ((const float4*)in)[grow * 32 + c4];

            const __nv_bfloat16 hx = __float2bfloat16_rn(v.x);
            const __nv_bfloat16 hy = __float2bfloat16_rn(v.y);
            const __nv_bfloat16 hz = __float2bfloat16_rn(v.z);
            const __nv_bfloat16 hw = __float2bfloat16_rn(v.w);
            const __nv_bfloat16 lx = __float2bfloat16_rn(v.x - __bfloat162float(hx));
            const __nv_bfloat16 ly = __float2bfloat16_rn(v.y - __bfloat162float(hy));
            const __nv_bfloat16 lz = __float2bfloat16_rn(v.z - __bfloat162float(hz));
            const __nv_bfloat16 lw = __float2bfloat16_rn(v.w - __bfloat162float(hw));

            uint2 hi, lo;
            hi.x = (uint32_t)__bfloat16_as_ushort(hx) | ((uint32_t)__bfloat16_as_ushort(hy) << 16);
            hi.y = (uint32_t)__bfloat16_as_ushort(hz) | ((uint32_t)__bfloat16_as_ushort(hw) << 16);
            lo.x = (uint32_t)__bfloat16_as_ushort(lx) | ((uint32_t)__bfloat16_as_ushort(ly) << 16);
            lo.y = (uint32_t)__bfloat16_as_ushort(lz) | ((uint32_t)__bfloat16_as_ushort(lw) << 16);

            __nv_bfloat16* sA = (__nv_bfloat16*)smem;
            *(uint2*)&sA[SA_HI + row * KS + c4 * 4] = hi;
            *(uint2*)&sA[SA_LO + row * KS + c4 * 4] = lo;
        }
        __syncthreads();

        #pragma unroll
        for (int mat = 0; mat < 2; mat++) {
            float acc[2][8][4];
            #pragma unroll
            for (int mt = 0; mt < 2; mt++)
                #pragma unroll
                for (int nt = 0; nt < 8; nt++)
                    #pragma unroll
                    for (int q = 0; q < 4; q++) acc[mt][nt][q] = 0.f;

            const uint32_t Bhi = SB0 + mat * 2 * IMG_ELEMS;
            const uint32_t Blo = Bhi + IMG_ELEMS;

            #pragma unroll
            for (int s = 0; s < 3; s++) {
                const uint32_t Ab = (s < 2) ? SA_HI : SA_LO;
                const uint32_t Bb = (s == 1) ? Blo : Bhi;
                #pragma unroll
                for (int kk = 0; kk < 8; kk++) {
                    uint32_t a0[4], a1[4];
                    const uint32_t aaddr = sb + 2u * (Ab + (row0 + lane_r) * KS + kk * 16 + lane_c8);
                    LDSM_X4(a0[0], a0[1], a0[2], a0[3], aaddr);
                    LDSM_X4(a1[0], a1[1], a1[2], a1[3], aaddr + 2u * 16 * KS);
                    #pragma unroll
                    for (int np = 0; np < 4; np++) {
                        const uint32_t baddr = sb + 2u * (Bb + (col0 + np * 16 + b_n) * KS + kk * 16 + b_k8);
                        uint32_t b0, b1, b2, b3;
                        LDSM_X4(b0, b1, b2, b3, baddr);
                        mma_bf16(acc[0][np * 2 + 0], a0, b0, b1);
                        mma_bf16(acc[0][np * 2 + 1], a0, b2, b3);
                        mma_bf16(acc[1][np * 2 + 0], a1, b0, b1);
                        mma_bf16(acc[1][np * 2 + 1], a1, b2, b3);
                    }
                }
            }

            float* out = mat ? outR : outL;
            #pragma unroll
            for (int mt = 0; mt < 2; mt++) {
                const int r = base + row0 + mt * 16 + (lane >> 2);
                #pragma unroll
                for (int nt = 0; nt < 8; nt++) {
                    const int c = col0 + nt * 8 + (lane & 3) * 2;
                    if (r < N_NODES)
                        *(float2*)&out[r * CH + c] = make_float2(acc[mt][nt][0], acc[mt][nt][1]);
                    if (r + 8 < N_NODES)
                        *(float2*)&out[(r + 8) * CH + c] = make_float2(acc[mt][nt][2], acc[mt][nt][3]);
                }
            }
        }
    }
}

// ---------------------------------------------------------------------------
// Fused edge-score + softmax + aggregation. Warp per destination node.
// ---------------------------------------------------------------------------
template <int H, bool ELU>
__global__ __launch_bounds__(256) void gather_fused(
    const float* __restrict__ xl, const float* __restrict__ xr,
    const float* __restrict__ att,
    const int* __restrict__ off, const int* __restrict__ srcs,
    const float* __restrict__ bias, float* __restrict__ out)
{
    const int node = (blockIdx.x * blockDim.x + threadIdx.x) >> 5;
    const int lane = threadIdx.x & 31;
    if (node >= N_NODES) return;

    const int s0 = off[node];
    const int s1 = off[node + 1];

    constexpr int G = 32 / H;

    const float4 b = ((const float4*)xr)[node * 32 + lane];
    const float4 w = ((const float4*)att)[lane];

    float  den = 0.f;
    float4 acc = make_float4(0.f, 0.f, 0.f, 0.f);

    int i = s0;
    for (; i + 4 <= s1; i += 4) {
        const int sa  = srcs[i + 0];
        const int sbn = srcs[i + 1];
        const int sc  = srcs[i + 2];
        const int sd  = srcs[i + 3];
        const float4 a0 = ((const float4*)xl)[sa  * 32 + lane];
        const float4 a1 = ((const float4*)xl)[sbn * 32 + lane];
        const float4 a2 = ((const float4*)xl)[sc  * 32 + lane];
        const float4 a3 = ((const float4*)xl)[sd  * 32 + lane];

        float p0, p1, p2, p3;
        {
            float t0, t1, t2, t3;
            t0 = a0.x + b.x; t0 = (t0 > 0.f) ? t0 : NEG_SLOPE * t0; p0  = t0 * w.x;
            t1 = a0.y + b.y; t1 = (t1 > 0.f) ? t1 : NEG_SLOPE * t1; p0 += t1 * w.y;
            t2 = a0.z + b.z; t2 = (t2 > 0.f) ? t2 : NEG_SLOPE * t2; p0 += t2 * w.z;
            t3 = a0.w + b.w; t3 = (t3 > 0.f) ? t3 : NEG_SLOPE * t3; p0 += t3 * w.w;
            t0 = a1.x + b.x; t0 = (t0 > 0.f) ? t0 : NEG_SLOPE * t0; p1  = t0 * w.x;
            t1 = a1.y + b.y; t1 = (t1 > 0.f) ? t1 : NEG_SLOPE * t1; p1 += t1 * w.y;
            t2 = a1.z + b.z; t2 = (t2 > 0.f) ? t2 : NEG_SLOPE * t2; p1 += t2 * w.z;
            t3 = a1.w + b.w; t3 = (t3 > 0.f) ? t3 : NEG_SLOPE * t3; p1 += t3 * w.w;
            t0 = a2.x + b.x; t0 = (t0 > 0.f) ? t0 : NEG_SLOPE * t0; p2  = t0 * w.x;
            t1 = a2.y + b.y; t1 = (t1 > 0.f) ? t1 : NEG_SLOPE * t1; p2 += t1 * w.y;
            t2 = a2.z + b.z; t2 = (t2 > 0.f) ? t2 : NEG_SLOPE * t2; p2 += t2 * w.z;
            t3 = a2.w + b.w; t3 = (t3 > 0.f) ? t3 : NEG_SLOPE * t3; p2 += t3 * w.w;
            t0 = a3.x + b.x; t0 = (t0 > 0.f) ? t0 : NEG_SLOPE * t0; p3  = t0 * w.x;
            t1 = a3.y + b.y; t1 = (t1 > 0.f) ? t1 : NEG_SLOPE * t1; p3 += t1 * w.y;
            t2 = a3.z + b.z; t2 = (t2 > 0.f) ? t2 : NEG_SLOPE * t2; p3 += t2 * w.z;
            t3 = a3.w + b.w; t3 = (t3 > 0.f) ? t3 : NEG_SLOPE * t3; p3 += t3 * w.w;
        }
        #pragma unroll
        for (int o = G / 2; o >= 1; o >>= 1) {
            p0 += __shfl_xor_sync(0xffffffffu, p0, o);
            p1 += __shfl_xor_sync(0xffffffffu, p1, o);
            p2 += __shfl_xor_sync(0xffffffffu, p2, o);
            p3 += __shfl_xor_sync(0xffffffffu, p3, o);
        }

        const float e0 = __expf(p0);
        const float e1 = __expf(p1);
        const float e2 = __expf(p2);
        const float e3 = __expf(p3);
        den  += (e0 + e1) + (e2 + e3);
        acc.x += e0 * a0.x + e1 * a1.x + e2 * a2.x + e3 * a3.x;
        acc.y += e0 * a0.y + e1 * a1.y + e2 * a2.y + e3 * a3.y;
        acc.z += e0 * a0.z + e1 * a1.z + e2 * a2.z + e3 * a3.z;
        acc.w += e0 * a0.w + e1 * a1.w + e2 * a2.w + e3 * a3.w;
    }

    for (; i < s1; i++) {
        const int s = srcs[i];
        const float4 a = ((const float4*)xl)[s * 32 + lane];

        float m0 = a.x + b.x, m1 = a.y + b.y, m2 = a.z + b.z, m3 = a.w + b.w;
        m0 = (m0 > 0.f) ? m0 : NEG_SLOPE * m0;
        m1 = (m1 > 0.f) ? m1 : NEG_SLOPE * m1;
        m2 = (m2 > 0.f) ? m2 : NEG_SLOPE * m2;
        m3 = (m3 > 0.f) ? m3 : NEG_SLOPE * m3;
        float p = m0 * w.x + m1 * w.y + m2 * w.z + m3 * w.w;
        #pragma unroll
        for (int o = G / 2; o >= 1; o >>= 1)
            p += __shfl_xor_sync(0xffffffffu, p, o);

        const float ex = __expf(p);
        den   += ex;
        acc.x += ex * a.x;
        acc.y += ex * a.y;
        acc.z += ex * a.z;
        acc.w += ex * a.w;
    }

    if (den == 0.f) den = 1.f;
    const float inv = 1.f / den;

    float o0 = acc.x * inv + bias[4 * lane + 0];
    float o1 = acc.y * inv + bias[4 * lane + 1];
    float o2 = acc.z * inv + bias[4 * lane + 2];
    float o3 = acc.w * inv + bias[4 * lane + 3];
    if (ELU) {
        o0 = (o0 > 0.f) ? o0 : expm1f(o0);
        o1 = (o1 > 0.f) ? o1 : expm1f(o1);
        o2 = (o2 > 0.f) ? o2 : expm1f(o2);
        o3 = (o3 > 0.f) ? o3 : expm1f(o3);
    }
    ((float4*)out)[node * 32 + lane] = make_float4(o0, o1, o2, o3);
}

// ---------------------------------------------------------------------------
// Launch — dual-stream fork/join inside graph capture.
// ---------------------------------------------------------------------------
extern "C" void kernel_launch(void* const* d_in, const int* in_sizes, int n_in,
                              void* d_out, int out_size)
{
    (void)in_sizes; (void)n_in; (void)out_size;

    const float* x    = (const float*)d_in[0];
    const int*   ei   = (const int*)  d_in[1];
    const float* W1l  = (const float*)d_in[2];
    const float* W1r  = (const float*)d_in[3];
    const float* att1 = (const float*)d_in[4];
    const float* b1   = (const float*)d_in[5];
    const float* W2l  = (const float*)d_in[6];
    const float* W2r  = (const float*)d_in[7];
    const float* att2 = (const float*)d_in[8];
    const float* b2   = (const float*)d_in[9];
    float* out = (float*)d_out;

    const int* src = ei;
    const int* dst = ei + E_EDGES;

    float *xl, *xr, *h;
    int *deg, *cur, *off, *srcs;
    __nv_bfloat16* img;
    cudaGetSymbolAddress((void**)&xl,   g_xl);
    cudaGetSymbolAddress((void**)&xr,   g_xr);
    cudaGetSymbolAddress((void**)&h,    g_h);
    cudaGetSymbolAddress((void**)&deg,  g_deg);
    cudaGetSymbolAddress((void**)&cur,  g_cur);
    cudaGetSymbolAddress((void**)&off,  g_off);
    cudaGetSymbolAddress((void**)&srcs, g_srcs);
    cudaGetSymbolAddress((void**)&img,  g_Bimg);

    cudaFuncSetAttribute(gemm_mma, cudaFuncAttributeMaxDynamicSharedMemorySize, SM_BYTES);

    static cudaStream_t s1 = nullptr;
    static cudaEvent_t ev_fork = nullptr, ev_g1 = nullptr;
    if (!s1) {
        cudaStreamCreateWithFlags(&s1, cudaStreamNonBlocking);
        cudaEventCreateWithFlags(&ev_fork, cudaEventDisableTiming);
        cudaEventCreateWithFlags(&ev_g1,   cudaEventDisableTiming);
    }

    const int EB4 = (E_EDGES / 4 + 255) / 256;      // 782
    const int NWB = (N_NODES * 32 + 255) / 256;

    // fork s1 from the capture (default) stream
    cudaEventRecord(ev_fork, 0);
    cudaStreamWaitEvent(s1, ev_fork, 0);

    // ---- s1: weight prep + layer-1 GEMM ----
    prep_w<<<256, 256, 0, s1>>>(W1l, W1r, W2l, W2r, img);
    gemm_mma<<<GEMM_GRID, 256, SM_BYTES, s1>>>(x, img, xl, xr);
    cudaEventRecord(ev_g1, s1);

    // ---- s0: CSR build (overlaps with s1) ----
    cudaMemsetAsync(deg, 0, N_NODES * sizeof(int));
    count_deg<<<EB4, 256>>>((const int4*)dst, deg);
    scan_deg<<<1, 1024>>>(deg, off, cur);
    scatter_csr<<<EB4, 256>>>((const int4*)src, (const int4*)dst, cur, srcs);

    // join: gather1 needs xl/xr (s1) + CSR (s0)
    cudaStreamWaitEvent(0, ev_g1, 0);

    // ---- Layer 1 (H=4, ELU) ----
    gather_fused<4, true><<<NWB, 256>>>(xl, xr, att1, off, srcs, b1, h);

    // ---- Layer 2 (H=1) ----
    gemm_mma<<<GEMM_GRID, 256, SM_BYTES>>>(h, img + 4 * IMG_ELEMS, xl, xr);
    gather_fused<1, false><<<NWB, 256>>>(xl, xr, att2, off, srcs, b2, out);
}

// round 13
// speedup vs baseline: 1.2823x; 1.2823x over previous
#include <cuda_runtime.h>
#include <cuda_bf16.h>
#include <math.h>
#include <stdint.h>

#define N_NODES 50000
#define E_EDGES 800000
#define CH 128
#define NEG_SLOPE 0.2f
#define N_TILES ((N_NODES + 127) / 128)   // 391
#define GEMM_GRID 148
#define SCAN_BLKS ((N_NODES + 1023) / 1024)   // 49

// ---------------- scratch (static device globals) ----------------
__device__ float g_xl[N_NODES * CH];
__device__ float g_xr[N_NODES * CH];
__device__ float g_h[N_NODES * CH];
__device__ int   g_deg[N_NODES];
__device__ int   g_cur[N_NODES];
__device__ int   g_off[N_NODES + 1];
__device__ int   g_srcs[E_EDGES];
__device__ int   g_bsum[SCAN_BLKS];
__device__ int   g_base[SCAN_BLKS + 1];
// weight images: [layer][Lhi, Llo, Rhi, Rlo], each [n=128][k stride 136] bf16
#define KS 136
#define IMG_ELEMS (128 * KS)            // 17408
__device__ __align__(16) __nv_bfloat16 g_Bimg[2 * 4 * IMG_ELEMS];

__device__ __forceinline__ uint32_t smem_u32(const void* p) {
    uint32_t a;
    asm("{ .reg .u64 t; cvta.to.shared.u64 t, %1; cvt.u32.u64 %0, t; }"
        : "=r"(a) : "l"(p));
    return a;
}

#define LDSM_X4(r0, r1, r2, r3, addr)                                         \
    asm volatile("ldmatrix.sync.aligned.m8n8.x4.shared.b16 {%0,%1,%2,%3}, [%4];" \
                 : "=r"(r0), "=r"(r1), "=r"(r2), "=r"(r3) : "r"(addr))

__device__ __forceinline__ void mma_bf16(float* c, const uint32_t* a,
                                         uint32_t b0, uint32_t b1) {
    asm volatile(
        "mma.sync.aligned.m16n8k16.row.col.f32.bf16.bf16.f32 "
        "{%0,%1,%2,%3}, {%4,%5,%6,%7}, {%8,%9}, {%0,%1,%2,%3};"
        : "+f"(c[0]), "+f"(c[1]), "+f"(c[2]), "+f"(c[3])
        : "r"(a[0]), "r"(a[1]), "r"(a[2]), "r"(a[3]), "r"(b0), "r"(b1));
}

// ============================ weight image prep ============================
__global__ __launch_bounds__(256) void prep_w(
    const float* __restrict__ W1l, const float* __restrict__ W1r,
    const float* __restrict__ W2l, const float* __restrict__ W2r,
    __nv_bfloat16* __restrict__ img)
{
    const int tid = blockIdx.x * 256 + threadIdx.x;   // 65536 total
    const int layer = tid >> 15;
    const int m     = (tid >> 14) & 1;
    const int e     = tid & 16383;
    const int k = e >> 7, n = e & 127;

    const float* W = layer ? (m ? W2r : W2l) : (m ? W1r : W1l);
    const float v = W[k * 128 + n];
    const __nv_bfloat16 hi = __float2bfloat16_rn(v);
    const __nv_bfloat16 lo = __float2bfloat16_rn(v - __bfloat162float(hi));

    const int base = (layer * 4 + m * 2) * IMG_ELEMS;
    img[base + n * KS + k]             = hi;
    img[base + IMG_ELEMS + n * KS + k] = lo;
}

// =============================== CSR build =================================
__global__ __launch_bounds__(256) void count_deg(const int4* __restrict__ dst4,
                                                 int* __restrict__ deg)
{
    const int i = blockIdx.x * 256 + threadIdx.x;
    if (i < E_EDGES / 4) {
        const int4 d = dst4[i];
        atomicAdd(&deg[d.x], 1);
        atomicAdd(&deg[d.y], 1);
        atomicAdd(&deg[d.z], 1);
        atomicAdd(&deg[d.w], 1);
    }
}

// --- 3-phase coalesced scan ---
__global__ __launch_bounds__(1024) void scan_sums(const int* __restrict__ deg,
                                                  int* __restrict__ bsum)
{
    __shared__ int ws[32];
    const int t = threadIdx.x, lane = t & 31, wid = t >> 5;
    const int idx = blockIdx.x * 1024 + t;
    int v = (idx < N_NODES) ? deg[idx] : 0;
    #pragma unroll
    for (int o = 16; o >= 1; o >>= 1) v += __shfl_xor_sync(0xffffffffu, v, o);
    if (lane == 0) ws[wid] = v;
    __syncthreads();
    if (t < 32) {
        int s = ws[t];
        #pragma unroll
        for (int o = 16; o >= 1; o >>= 1) s += __shfl_xor_sync(0xffffffffu, s, o);
        if (t == 0) bsum[blockIdx.x] = s;
    }
}

// single warp: exclusive scan of SCAN_BLKS block sums (2 per lane)
__global__ __launch_bounds__(32) void scan_bases(const int* __restrict__ bsum,
                                                 int* __restrict__ base,
                                                 int* __restrict__ off)
{
    const int l = threadIdx.x;
    const int i0 = 2 * l, i1 = 2 * l + 1;
    const int v0 = (i0 < SCAN_BLKS) ? bsum[i0] : 0;
    const int v1 = (i1 < SCAN_BLKS) ? bsum[i1] : 0;
    const int pair = v0 + v1;
    int s = pair;
    #pragma unroll
    for (int o = 1; o < 32; o <<= 1) {
        int t = __shfl_up_sync(0xffffffffu, s, o);
        if (l >= o) s += t;
    }
    const int excl = s - pair;
    if (i0 <= SCAN_BLKS) base[i0] = excl;
    if (i1 <= SCAN_BLKS) base[i1] = excl + v0;
    if (l == 31) off[N_NODES] = s;   // total
}

__global__ __launch_bounds__(1024) void scan_apply(const int* __restrict__ deg,
                                                   const int* __restrict__ base,
                                                   int* __restrict__ off,
                                                   int* __restrict__ cur)
{
    __shared__ int wsum[32];
    const int t = threadIdx.x, lane = t & 31, wid = t >> 5;
    const int idx = blockIdx.x * 1024 + t;
    const int v = (idx < N_NODES) ? deg[idx] : 0;
    int s = v;
    #pragma unroll
    for (int o = 1; o < 32; o <<= 1) {
        int u = __shfl_up_sync(0xffffffffu, s, o);
        if (lane >= o) s += u;
    }
    if (lane == 31) wsum[wid] = s;
    __syncthreads();
    if (wid == 0) {
        int ws = wsum[lane];
        #pragma unroll
        for (int o = 1; o < 32; o <<= 1) {
            int u = __shfl_up_sync(0xffffffffu, ws, o);
            if (lane >= o) ws += u;
        }
        wsum[lane] = ws;
    }
    __syncthreads();
    if (idx < N_NODES) {
        const int excl = s - v + (wid > 0 ? wsum[wid - 1] : 0) + base[blockIdx.x];
        off[idx] = excl;
        cur[idx] = excl;
    }
}

__global__ __launch_bounds__(256) void scatter_csr(
    const int4* __restrict__ src4, const int4* __restrict__ dst4,
    int* __restrict__ cur, int* __restrict__ srcs)
{
    const int i = blockIdx.x * 256 + threadIdx.x;
    if (i >= E_EDGES / 4) return;
    const int4 s = src4[i];
    const int4 d = dst4[i];
    srcs[atomicAdd(&cur[d.x], 1)] = s.x;
    srcs[atomicAdd(&cur[d.y], 1)] = s.y;
    srcs[atomicAdd(&cur[d.z], 1)] = s.z;
    srcs[atomicAdd(&cur[d.w], 1)] = s.w;
}

// ====== persistent mma.sync bf16 split-3 dual GEMM (256 thr, copy-once) ====
#define SA_HI 0
#define SA_LO IMG_ELEMS
#define SB0   (2 * IMG_ELEMS)
#define SM_BYTES (6 * IMG_ELEMS * 2)    // 208896

__global__ __launch_bounds__(256, 1)
void gemm_mma(const float* __restrict__ in, const __nv_bfloat16* __restrict__ img,
              float* __restrict__ outL, float* __restrict__ outR)
{
    extern __shared__ char smem[];
    const uint32_t sb = smem_u32(smem);
    const int tid = threadIdx.x;
    const int lane = tid & 31;
    const int wid = tid >> 5;

    // ---- B: copy 4 pre-split images ONCE ----
    {
        const uint4* gi = (const uint4*)img;
        uint4* si = (uint4*)(smem + SB0 * 2);
        #pragma unroll
        for (int i = 0; i < 34; i++) {
            const int idx = i * 256 + tid;        // 8704 uint4
            si[idx] = gi[idx];
        }
    }

    const int wm = wid & 3, wn = wid >> 2;
    const int row0 = wm * 32, col0 = wn * 64;
    const int lane_r  = lane & 15;
    const int lane_c8 = (lane >> 4) * 8;
    const int sub = lane & 7, sel = lane >> 3;
    const int b_n  = sub + ((sel & 2) ? 8 : 0);
    const int b_k8 = (sel & 1) ? 8 : 0;

    for (int t = blockIdx.x; t < N_TILES; t += GEMM_GRID) {
        const int base = t * 128;

        __syncthreads();

        // ---- A: load fp32 rows, split bf16 hi/lo, store padded ----
        #pragma unroll
        for (int i = 0; i < 16; i++) {
            const int chunk = i * 256 + tid;
            const int row = chunk >> 5;
            const int c4  = chunk & 31;
            int grow = base + row;
            if (grow >= N_NODES) grow = N_NODES - 1;
            const float4 v = ((const float4*)in)[grow * 32 + c4];

            const __nv_bfloat16 hx = __float2bfloat16_rn(v.x);
            const __nv_bfloat16 hy = __float2bfloat16_rn(v.y);
            const __nv_bfloat16 hz = __float2bfloat16_rn(v.z);
            const __nv_bfloat16 hw = __float2bfloat16_rn(v.w);
            const __nv_bfloat16 lx = __float2bfloat16_rn(v.x - __bfloat162float(hx));
            const __nv_bfloat16 ly = __float2bfloat16_rn(v.y - __bfloat162float(hy));
            const __nv_bfloat16 lz = __float2bfloat16_rn(v.z - __bfloat162float(hz));
            const __nv_bfloat16 lw = __float2bfloat16_rn(v.w - __bfloat162float(hw));

            uint2 hi, lo;
            hi.x = (uint32_t)__bfloat16_as_ushort(hx) | ((uint32_t)__bfloat16_as_ushort(hy) << 16);
            hi.y = (uint32_t)__bfloat16_as_ushort(hz) | ((uint32_t)__bfloat16_as_ushort(hw) << 16);
            lo.x = (uint32_t)__bfloat16_as_ushort(lx) | ((uint32_t)__bfloat16_as_ushort(ly) << 16);
            lo.y = (uint32_t)__bfloat16_as_ushort(lz) | ((uint32_t)__bfloat16_as_ushort(lw) << 16);

            __nv_bfloat16* sA = (__nv_bfloat16*)smem;
            *(uint2*)&sA[SA_HI + row * KS + c4 * 4] = hi;
            *(uint2*)&sA[SA_LO + row * KS + c4 * 4] = lo;
        }
        __syncthreads();

        #pragma unroll
        for (int mat = 0; mat < 2; mat++) {
            float acc[2][8][4];
            #pragma unroll
            for (int mt = 0; mt < 2; mt++)
                #pragma unroll
                for (int nt = 0; nt < 8; nt++)
                    #pragma unroll
                    for (int q = 0; q < 4; q++) acc[mt][nt][q] = 0.f;

            const uint32_t Bhi = SB0 + mat * 2 * IMG_ELEMS;
            const uint32_t Blo = Bhi + IMG_ELEMS;

            #pragma unroll
            for (int s = 0; s < 3; s++) {
                const uint32_t Ab = (s < 2) ? SA_HI : SA_LO;
                const uint32_t Bb = (s == 1) ? Blo : Bhi;
                #pragma unroll
                for (int kk = 0; kk < 8; kk++) {
                    uint32_t a0[4], a1[4];
                    const uint32_t aaddr = sb + 2u * (Ab + (row0 + lane_r) * KS + kk * 16 + lane_c8);
                    LDSM_X4(a0[0], a0[1], a0[2], a0[3], aaddr);
                    LDSM_X4(a1[0], a1[1], a1[2], a1[3], aaddr + 2u * 16 * KS);
                    #pragma unroll
                    for (int np = 0; np < 4; np++) {
                        const uint32_t baddr = sb + 2u * (Bb + (col0 + np * 16 + b_n) * KS + kk * 16 + b_k8);
                        uint32_t b0, b1, b2, b3;
                        LDSM_X4(b0, b1, b2, b3, baddr);
                        mma_bf16(acc[0][np * 2 + 0], a0, b0, b1);
                        mma_bf16(acc[0][np * 2 + 1], a0, b2, b3);
                        mma_bf16(acc[1][np * 2 + 0], a1, b0, b1);
                        mma_bf16(acc[1][np * 2 + 1], a1, b2, b3);
                    }
                }
            }

            float* out = mat ? outR : outL;
            #pragma unroll
            for (int mt = 0; mt < 2; mt++) {
                const int r = base + row0 + mt * 16 + (lane >> 2);
                #pragma unroll
                for (int nt = 0; nt < 8; nt++) {
                    const int c = col0 + nt * 8 + (lane & 3) * 2;
                    if (r < N_NODES)
                        *(float2*)&out[r * CH + c] = make_float2(acc[mt][nt][0], acc[mt][nt][1]);
                    if (r + 8 < N_NODES)
                        *(float2*)&out[(r + 8) * CH + c] = make_float2(acc[mt][nt][2], acc[mt][nt][3]);
                }
            }
        }
    }
}

// ---------------------------------------------------------------------------
// Fused edge-score + softmax + aggregation. Warp per destination node.
// ---------------------------------------------------------------------------
template <int H, bool ELU>
__global__ __launch_bounds__(256) void gather_fused(
    const float* __restrict__ xl, const float* __restrict__ xr,
    const float* __restrict__ att,
    const int* __restrict__ off, const int* __restrict__ srcs,
    const float* __restrict__ bias, float* __restrict__ out)
{
    const int node = (blockIdx.x * blockDim.x + threadIdx.x) >> 5;
    const int lane = threadIdx.x & 31;
    if (node >= N_NODES) return;

    const int s0 = off[node];
    const int s1 = off[node + 1];

    constexpr int G = 32 / H;

    const float4 b = ((const float4*)xr)[node * 32 + lane];
    const float4 w = ((const float4*)att)[lane];

    float  den = 0.f;
    float4 acc = make_float4(0.f, 0.f, 0.f, 0.f);

    int i = s0;
    for (; i + 4 <= s1; i += 4) {
        const int sa  = srcs[i + 0];
        const int sbn = srcs[i + 1];
        const int sc  = srcs[i + 2];
        const int sd  = srcs[i + 3];
        const float4 a0 = ((const float4*)xl)[sa  * 32 + lane];
        const float4 a1 = ((const float4*)xl)[sbn * 32 + lane];
        const float4 a2 = ((const float4*)xl)[sc  * 32 + lane];
        const float4 a3 = ((const float4*)xl)[sd  * 32 + lane];

        float p0, p1, p2, p3;
        {
            float t0, t1, t2, t3;
            t0 = a0.x + b.x; t0 = (t0 > 0.f) ? t0 : NEG_SLOPE * t0; p0  = t0 * w.x;
            t1 = a0.y + b.y; t1 = (t1 > 0.f) ? t1 : NEG_SLOPE * t1; p0 += t1 * w.y;
            t2 = a0.z + b.z; t2 = (t2 > 0.f) ? t2 : NEG_SLOPE * t2; p0 += t2 * w.z;
            t3 = a0.w + b.w; t3 = (t3 > 0.f) ? t3 : NEG_SLOPE * t3; p0 += t3 * w.w;
            t0 = a1.x + b.x; t0 = (t0 > 0.f) ? t0 : NEG_SLOPE * t0; p1  = t0 * w.x;
            t1 = a1.y + b.y; t1 = (t1 > 0.f) ? t1 : NEG_SLOPE * t1; p1 += t1 * w.y;
            t2 = a1.z + b.z; t2 = (t2 > 0.f) ? t2 : NEG_SLOPE * t2; p1 += t2 * w.z;
            t3 = a1.w + b.w; t3 = (t3 > 0.f) ? t3 : NEG_SLOPE * t3; p1 += t3 * w.w;
            t0 = a2.x + b.x; t0 = (t0 > 0.f) ? t0 : NEG_SLOPE * t0; p2  = t0 * w.x;
            t1 = a2.y + b.y; t1 = (t1 > 0.f) ? t1 : NEG_SLOPE * t1; p2 += t1 * w.y;
            t2 = a2.z + b.z; t2 = (t2 > 0.f) ? t2 : NEG_SLOPE * t2; p2 += t2 * w.z;
            t3 = a2.w + b.w; t3 = (t3 > 0.f) ? t3 : NEG_SLOPE * t3; p2 += t3 * w.w;
            t0 = a3.x + b.x; t0 = (t0 > 0.f) ? t0 : NEG_SLOPE * t0; p3  = t0 * w.x;
            t1 = a3.y + b.y; t1 = (t1 > 0.f) ? t1 : NEG_SLOPE * t1; p3 += t1 * w.y;
            t2 = a3.z + b.z; t2 = (t2 > 0.f) ? t2 : NEG_SLOPE * t2; p3 += t2 * w.z;
            t3 = a3.w + b.w; t3 = (t3 > 0.f) ? t3 : NEG_SLOPE * t3; p3 += t3 * w.w;
        }
        #pragma unroll
        for (int o = G / 2; o >= 1; o >>= 1) {
            p0 += __shfl_xor_sync(0xffffffffu, p0, o);
            p1 += __shfl_xor_sync(0xffffffffu, p1, o);
            p2 += __shfl_xor_sync(0xffffffffu, p2, o);
            p3 += __shfl_xor_sync(0xffffffffu, p3, o);
        }

        const float e0 = __expf(p0);
        const float e1 = __expf(p1);
        const float e2 = __expf(p2);
        const float e3 = __expf(p3);
        den  += (e0 + e1) + (e2 + e3);
        acc.x += e0 * a0.x + e1 * a1.x + e2 * a2.x + e3 * a3.x;
        acc.y += e0 * a0.y + e1 * a1.y + e2 * a2.y + e3 * a3.y;
        acc.z += e0 * a0.z + e1 * a1.z + e2 * a2.z + e3 * a3.z;
        acc.w += e0 * a0.w + e1 * a1.w + e2 * a2.w + e3 * a3.w;
    }

    for (; i < s1; i++) {
        const int s = srcs[i];
        const float4 a = ((const float4*)xl)[s * 32 + lane];

        float m0 = a.x + b.x, m1 = a.y + b.y, m2 = a.z + b.z, m3 = a.w + b.w;
        m0 = (m0 > 0.f) ? m0 : NEG_SLOPE * m0;
        m1 = (m1 > 0.f) ? m1 : NEG_SLOPE * m1;
        m2 = (m2 > 0.f) ? m2 : NEG_SLOPE * m2;
        m3 = (m3 > 0.f) ? m3 : NEG_SLOPE * m3;
        float p = m0 * w.x + m1 * w.y + m2 * w.z + m3 * w.w;
        #pragma unroll
        for (int o = G / 2; o >= 1; o >>= 1)
            p += __shfl_xor_sync(0xffffffffu, p, o);

        const float ex = __expf(p);
        den   += ex;
        acc.x += ex * a.x;
        acc.y += ex * a.y;
        acc.z += ex * a.z;
        acc.w += ex * a.w;
    }

    if (den == 0.f) den = 1.f;
    const float inv = 1.f / den;

    float o0 = acc.x * inv + bias[4 * lane + 0];
    float o1 = acc.y * inv + bias[4 * lane + 1];
    float o2 = acc.z * inv + bias[4 * lane + 2];
    float o3 = acc.w * inv + bias[4 * lane + 3];
    if (ELU) {
        o0 = (o0 > 0.f) ? o0 : expm1f(o0);
        o1 = (o1 > 0.f) ? o1 : expm1f(o1);
        o2 = (o2 > 0.f) ? o2 : expm1f(o2);
        o3 = (o3 > 0.f) ? o3 : expm1f(o3);
    }
    ((float4*)out)[node * 32 + lane] = make_float4(o0, o1, o2, o3);
}

// ---------------------------------------------------------------------------
// Launch — dual-stream fork/join inside graph capture.
// ---------------------------------------------------------------------------
extern "C" void kernel_launch(void* const* d_in, const int* in_sizes, int n_in,
                              void* d_out, int out_size)
{
    (void)in_sizes; (void)n_in; (void)out_size;

    const float* x    = (const float*)d_in[0];
    const int*   ei   = (const int*)  d_in[1];
    const float* W1l  = (const float*)d_in[2];
    const float* W1r  = (const float*)d_in[3];
    const float* att1 = (const float*)d_in[4];
    const float* b1   = (const float*)d_in[5];
    const float* W2l  = (const float*)d_in[6];
    const float* W2r  = (const float*)d_in[7];
    const float* att2 = (const float*)d_in[8];
    const float* b2   = (const float*)d_in[9];
    float* out = (float*)d_out;

    const int* src = ei;
    const int* dst = ei + E_EDGES;

    float *xl, *xr, *h;
    int *deg, *cur, *off, *srcs, *bsum, *base;
    __nv_bfloat16* img;
    cudaGetSymbolAddress((void**)&xl,   g_xl);
    cudaGetSymbolAddress((void**)&xr,   g_xr);
    cudaGetSymbolAddress((void**)&h,    g_h);
    cudaGetSymbolAddress((void**)&deg,  g_deg);
    cudaGetSymbolAddress((void**)&cur,  g_cur);
    cudaGetSymbolAddress((void**)&off,  g_off);
    cudaGetSymbolAddress((void**)&srcs, g_srcs);
    cudaGetSymbolAddress((void**)&bsum, g_bsum);
    cudaGetSymbolAddress((void**)&base, g_base);
    cudaGetSymbolAddress((void**)&img,  g_Bimg);

    cudaFuncSetAttribute(gemm_mma, cudaFuncAttributeMaxDynamicSharedMemorySize, SM_BYTES);

    static cudaStream_t s1 = nullptr;
    static cudaEvent_t ev_fork = nullptr, ev_g1 = nullptr;
    if (!s1) {
        cudaStreamCreateWithFlags(&s1, cudaStreamNonBlocking);
        cudaEventCreateWithFlags(&ev_fork, cudaEventDisableTiming);
        cudaEventCreateWithFlags(&ev_g1,   cudaEventDisableTiming);
    }

    const int EB4 = (E_EDGES / 4 + 255) / 256;      // 782
    const int NWB = (N_NODES * 32 + 255) / 256;

    // fork s1 from the capture (default) stream
    cudaEventRecord(ev_fork, 0);
    cudaStreamWaitEvent(s1, ev_fork, 0);

    // ---- s1: weight prep + layer-1 GEMM ----
    prep_w<<<256, 256, 0, s1>>>(W1l, W1r, W2l, W2r, img);
    gemm_mma<<<GEMM_GRID, 256, SM_BYTES, s1>>>(x, img, xl, xr);
    cudaEventRecord(ev_g1, s1);

    // ---- s0: CSR build (overlaps with s1) ----
    cudaMemsetAsync(deg, 0, N_NODES * sizeof(int));
    count_deg<<<EB4, 256>>>((const int4*)dst, deg);
    scan_sums<<<SCAN_BLKS, 1024>>>(deg, bsum);
    scan_bases<<<1, 32>>>(bsum, base, off);
    scan_apply<<<SCAN_BLKS, 1024>>>(deg, base, off, cur);
    scatter_csr<<<EB4, 256>>>((const int4*)src, (const int4*)dst, cur, srcs);

    // join: gather1 needs xl/xr (s1) + CSR (s0)
    cudaStreamWaitEvent(0, ev_g1, 0);

    // ---- Layer 1 (H=4, ELU) ----
    gather_fused<4, true><<<NWB, 256>>>(xl, xr, att1, off, srcs, b1, h);

    // ---- Layer 2 (H=1) ----
    gemm_mma<<<GEMM_GRID, 256, SM_BYTES>>>(h, img + 4 * IMG_ELEMS, xl, xr);
    gather_fused<1, false><<<NWB, 256>>>(xl, xr, att2, off, srcs, b2, out);
}